// round 9
// baseline (speedup 1.0000x reference)
#include <cuda_runtime.h>

#define DEGREE 20

// Rescaled Clenshaw evaluation of sum_k W_k * P_k(x), then * (1 - x^2).
//
//   d_k = cp_k + x d_{k+1} + g_k d_{k+2},  S = d_0
//   cp_k = W_k * C(2k,k)/2^k,  g_k = -(k+1)^2/((2k+1)(2k+3))  (literal ->
//   FFMA-imm rt1; the x-FMA is 3-reg rt2 -> 63 fma-pipe cyc / warp-elem).
//
// R1: 32-reg cap spilled cp[] (LDL in loop).
// R3: occ==issue -> latency-bound (MLP=1).
// R4: 4 chains, 6.4 w/SMSP -> 18.6us, issue 69.5%.
// R7/R8: packed f32x2 rt=3 from 64-bit RF banking (3 even + 3 odd distinct
//     banks per FFMA2) -> same 63 cyc/elem pipe floor as scalar; fewer
//     chains dropped issue to ~40%; dur pinned 18.5us in all configs.
// R9: scalar form, 8 independent chains/thread (2 x float4 per iteration,
//     depth-1 prefetch), 4 blocks/SM. warps/SMSP x chains = 64 (2.5x R4)
//     to cover the 4-cyc dependent-FMA chain latency and saturate issue.

__device__ __forceinline__ float legendre_eval(float xx, const float* __restrict__ cp) {
    float d1 = 0.0f, d2 = 0.0f;
#pragma unroll
    for (int k = DEGREE; k >= 0; --k) {
        float g = -(float)((k + 1) * (k + 1)) / (float)((2 * k + 1) * (2 * k + 3));
        float u = fmaf(g, d2, cp[k]);   // FFMA-imm (g literal multiplier)
        float d0 = fmaf(xx, d1, u);     // FFMA 3-reg
        d2 = d1;
        d1 = d0;
    }
    float bc = fmaf(-xx, xx, 1.0f);     // 1 - x^2
    return d1 * bc;
}

__global__ __launch_bounds__(256, 4) void legendre_kernel(
    const float* __restrict__ x, const float* __restrict__ W,
    float* __restrict__ out, int n)
{
    // Per-thread scaled coefficients: cp[k] = W[k] * M_k,
    // M_k = prod_{j=1..k} (2j-1)/j (ratios fold to immediates).
    float cp[DEGREE + 1];
    {
        float M = 1.0f;
        cp[0] = __ldg(&W[0]);
#pragma unroll
        for (int k = 1; k <= DEGREE; ++k) {
            M *= (float)(2 * k - 1) / (float)k;
            cp[k] = __ldg(&W[k]) * M;
        }
    }

    const int tid = blockIdx.x * blockDim.x + threadIdx.x;
    const int stride = gridDim.x * blockDim.x;
    const int n8 = n >> 3;   // chunks of 8 floats (2 x float4)

    const float4* __restrict__ x4 = (const float4*)x;
    float4* __restrict__ o4 = (float4*)out;

    // 8 independent Clenshaw chains per iteration; next iteration's two
    // LDG.128 issued before this iteration's ~340-cycle compute block.
    int i = tid;
    if (i < n8) {
        float4 a0 = x4[2 * i];
        float4 a1 = x4[2 * i + 1];
        for (; i + stride < n8; i += stride) {
            const int j = i + stride;
            float4 b0 = x4[2 * j];      // prefetch (independent of compute)
            float4 b1 = x4[2 * j + 1];
            float4 r0, r1;
            r0.x = legendre_eval(a0.x, cp);
            r0.y = legendre_eval(a0.y, cp);
            r0.z = legendre_eval(a0.z, cp);
            r0.w = legendre_eval(a0.w, cp);
            r1.x = legendre_eval(a1.x, cp);
            r1.y = legendre_eval(a1.y, cp);
            r1.z = legendre_eval(a1.z, cp);
            r1.w = legendre_eval(a1.w, cp);
            o4[2 * i] = r0;
            o4[2 * i + 1] = r1;
            a0 = b0;
            a1 = b1;
        }
        float4 r0, r1;
        r0.x = legendre_eval(a0.x, cp);
        r0.y = legendre_eval(a0.y, cp);
        r0.z = legendre_eval(a0.z, cp);
        r0.w = legendre_eval(a0.w, cp);
        r1.x = legendre_eval(a1.x, cp);
        r1.y = legendre_eval(a1.y, cp);
        r1.z = legendre_eval(a1.z, cp);
        r1.w = legendre_eval(a1.w, cp);
        o4[2 * i] = r0;
        o4[2 * i + 1] = r1;
    }

    // Scalar tail (n % 8 != 0) — not hit for n = 8,000,000 but kept correct.
    for (int j = (n8 << 3) + tid; j < n; j += stride) {
        out[j] = legendre_eval(x[j], cp);
    }
}

extern "C" void kernel_launch(void* const* d_in, const int* in_sizes, int n_in,
                              void* d_out, int out_size) {
    // Identify W by its element count (DEGREE+1); x is the big array.
    const float* x = (const float*)d_in[0];
    const float* W = (const float*)d_in[1];
    if (n_in >= 2 && in_sizes[0] == DEGREE + 1 && in_sizes[1] != DEGREE + 1) {
        x = (const float*)d_in[1];
        W = (const float*)d_in[0];
    }
    float* out = (float*)d_out;
    int n = out_size;

    // 592 = 4 resident blocks/SM on 148 SMs (64-reg budget); ~6.6 chunk
    // iterations/thread amortizes the coefficient prologue.
    legendre_kernel<<<592, 256>>>(x, W, out, n);
}